// round 4
// baseline (speedup 1.0000x reference)
#include <cuda_runtime.h>
#include <cstdint>

// Problem constants (fixed by the dataset)
#define BATCH 4
#define NCAPS 32          // B_
#define CIN   32          // C_
#define KK    3
#define WSP   14
#define HH    16          // 4x4 pose
#define OHW   29
#define CJI   (CIN*WSP*WSP)     // 6272
#define NKL   (NCAPS*KK*KK)     // 288
#define OUT_ELEMS (BATCH*NCAPS*OHW*OHW*HH)   // 1,722,368
#define SV_N4 (BATCH*CJI*HH/4)               // 100,352

#define CH    8                 // channels per smem chunk
#define NCHUNK (CIN/CH)         // 4

typedef unsigned long long u64;

// sqrt(var) scratch — allocation-free (__device__ global)
__device__ float g_sv[BATCH*CJI*HH];

__device__ __forceinline__ u64 ffma2(u64 a, u64 b, u64 c) {
    u64 d; asm("fma.rn.f32x2 %0, %1, %2, %3;" : "=l"(d) : "l"(a), "l"(b), "l"(c));
    return d;
}

// Fused prep: zero output + sqrt(var)
__global__ void k_prep(const float* __restrict__ var, float4* __restrict__ out) {
    int idx = blockIdx.x*blockDim.x + threadIdx.x;
    if (idx < OUT_ELEMS/4) out[idx] = make_float4(0.f,0.f,0.f,0.f);
    if (idx < SV_N4) {
        float4 v = reinterpret_cast<const float4*>(var)[idx];
        reinterpret_cast<float4*>(g_sv)[idx] =
            make_float4(sqrtf(v.x), sqrtf(v.y), sqrtf(v.z), sqrtf(v.w));
    }
}

// Main: block = (n, j, b); thread t = kl*14 + i (126 active of 128).
// Sequential c-reduction in registers with packed f32x2 math:
//   votes(v,:) = fma2(sv, nz, mu)                (8 FFMA2)
//   acc(u,:)  += {w_uv,w_uv} * votes(v,:)        (32 FFMA2)
// Weights pre-duplicated in smem as u64 {w,w}; mu/sv staged in smem per
// 8-channel chunk; noise streamed via __ldcs with 1-deep prefetch.
__global__ __launch_bounds__(128, 5)
void k_main(const float* __restrict__ poses,
            const float* __restrict__ Wt,
            const float* __restrict__ noise,
            float* __restrict__ out)
{
    const int n = blockIdx.x;
    const int j = blockIdx.y;
    const int b = blockIdx.z;
    const int t = threadIdx.x;

    extern __shared__ __align__(16) char shraw[];
    u64*    sW2  = reinterpret_cast<u64*>(shraw);             // [9][CH][16] u64 = 9216 B
    float4* sMu4 = reinterpret_cast<float4*>(shraw + 9216);   // [CH][14][5] f4  = 8960 B
    float4* sSv4 = sMu4 + CH*14*5;                            // same            = 8960 B

    const int kl = t / 14;           // 0..8
    const int k  = kl / 3;
    const int l  = kl - k*3;
    const int i  = t - kl*14;        // 0..13
    const bool active = (t < 126);

    // noise f4 base: ((b*288 + n*9 + kl)*6272 + j*14 + i) * 4
    const float4* np4 = reinterpret_cast<const float4*>(noise)
        + ((size_t)(b*NKL + n*9 + (active ? kl : 0)) * CJI + (size_t)(j*WSP + i)) * 4;
    // mu f4 base for this (b,j): c stride 784 f4
    const float4* mu_g = reinterpret_cast<const float4*>(poses)
        + ((size_t)b*CIN*WSP*WSP + (size_t)j*WSP) * 4;
    const float4* sv_g = reinterpret_cast<const float4*>(g_sv)
        + ((size_t)b*CJI + (size_t)j*WSP) * 4;
    // Wt scalar base for this n
    const float* wt_g = Wt + (size_t)n * 9 * CIN * HH;

    u64 A[8];
    #pragma unroll
    for (int x = 0; x < 8; x++) A[x] = 0ull;

    // prefetch noise for c=0
    u64 PN[8];
    if (active) {
        const ulonglong2* p = reinterpret_cast<const ulonglong2*>(np4);
        #pragma unroll
        for (int q = 0; q < 4; q++) {
            ulonglong2 z = __ldcs(p + q);
            PN[q*2] = z.x; PN[q*2+1] = z.y;
        }
    }

    #pragma unroll 1
    for (int cp = 0; cp < NCHUNK; cp++) {
        __syncthreads();   // previous chunk fully consumed
        // ---- stage duplicated weights for channels [cp*CH, cp*CH+CH) ----
        // 9*CH*16 = 1152 scalars, 9 per thread
        {
            #pragma unroll
            for (int it = 0; it < 9; it++) {
                int idx  = t + it*128;
                int klw  = idx >> 7;          // idx/128
                int rem  = idx & 127;
                int cc   = rem >> 4;
                int uv   = rem & 15;
                float w  = __ldg(&wt_g[((klw*CIN) + cp*CH + cc)*HH + uv]);
                float2 d = make_float2(w, w);
                reinterpret_cast<float2*>(sW2)[idx] = d;
            }
        }
        // ---- stage mu/sv: CH*14*4 = 448 f4 each ----
        #pragma unroll
        for (int it = 0; it < 4; it++) {
            int idx = t + it*128;
            if (idx < CH*56) {
                int c   = idx / 56;
                int rem = idx - c*56;
                int is  = rem >> 2;
                int q   = rem & 3;
                size_t g = (size_t)(cp*CH + c) * 784 + (size_t)(is*4 + q);
                int sidx = (c*14 + is)*5 + q;    // pitch-5 f4 padding
                sMu4[sidx] = __ldg(&mu_g[g]);
                sSv4[sidx] = __ldg(&sv_g[g]);
            }
        }
        __syncthreads();

        if (active) {
            #pragma unroll
            for (int cc = 0; cc < CH; cc++) {
                const int c_abs = cp*CH + cc;

                // consume prefetched noise
                u64 NZ[8];
                #pragma unroll
                for (int x = 0; x < 8; x++) NZ[x] = PN[x];

                // prefetch next channel's noise
                if (c_abs + 1 < CIN) {
                    const ulonglong2* p =
                        reinterpret_cast<const ulonglong2*>(np4 + (size_t)(c_abs+1)*784);
                    #pragma unroll
                    for (int q = 0; q < 4; q++) {
                        ulonglong2 z = __ldcs(p + q);
                        PN[q*2] = z.x; PN[q*2+1] = z.y;
                    }
                }

                const int sb = (cc*14 + i)*5;
                const ulonglong2* mp = reinterpret_cast<const ulonglong2*>(sMu4 + sb);
                const ulonglong2* sp = reinterpret_cast<const ulonglong2*>(sSv4 + sb);

                u64 V[8];
                #pragma unroll
                for (int v = 0; v < 4; v++) {
                    ulonglong2 m = mp[v];
                    ulonglong2 s = sp[v];
                    V[v*2]   = ffma2(s.x, NZ[v*2],   m.x);
                    V[v*2+1] = ffma2(s.y, NZ[v*2+1], m.y);
                }

                const u64* wrow = sW2 + (kl*CH + cc)*16;
                #pragma unroll
                for (int u = 0; u < 4; u++) {
                    const ulonglong2* wp = reinterpret_cast<const ulonglong2*>(wrow + u*4);
                    ulonglong2 w01 = wp[0];
                    ulonglong2 w23 = wp[1];
                    A[u*2]   = ffma2(w01.x, V[0], A[u*2]);
                    A[u*2+1] = ffma2(w01.x, V[1], A[u*2+1]);
                    A[u*2]   = ffma2(w01.y, V[2], A[u*2]);
                    A[u*2+1] = ffma2(w01.y, V[3], A[u*2+1]);
                    A[u*2]   = ffma2(w23.x, V[4], A[u*2]);
                    A[u*2+1] = ffma2(w23.x, V[5], A[u*2+1]);
                    A[u*2]   = ffma2(w23.y, V[6], A[u*2]);
                    A[u*2+1] = ffma2(w23.y, V[7], A[u*2+1]);
                }
            }
        }
    }

    if (active) {
        const int r  = 2*i + k;      // output row
        const int cl = 2*j + l;      // output col
        float* dst = out + (((size_t)(b*NCAPS + n)*OHW + r)*OHW + cl)*HH;
        #pragma unroll
        for (int x = 0; x < 8; x++) {
            float2 f = *reinterpret_cast<float2*>(&A[x]);
            atomicAdd(dst + x*2 + 0, f.x);
            atomicAdd(dst + x*2 + 1, f.y);
        }
    }
}

extern "C" void kernel_launch(void* const* d_in, const int* in_sizes, int n_in,
                              void* d_out, int out_size) {
    const float* poses = (const float*)d_in[0];
    const float* var   = (const float*)d_in[1];
    const float* Wt    = (const float*)d_in[2];
    const float* noise = (const float*)d_in[3];
    float* out = (float*)d_out;
    (void)in_sizes; (void)n_in; (void)out_size;

    const int SMEM = 9216 + 8960 + 8960;   // 27,136 B

    k_prep<<<(OUT_ELEMS/4 + 255)/256, 256>>>(var, (float4*)out);
    k_main<<<dim3(NCAPS, WSP, BATCH), 128, SMEM>>>(poses, Wt, noise, out);
}